// round 14
// baseline (speedup 1.0000x reference)
#include <cuda_runtime.h>
#include <cstdint>

#define B_    16
#define D_    512
#define L_    3000
#define NE_   1024
#define LP    3072
#define ZQ_ELEMS  ((size_t)B_ * D_ * L_)
#define IND_ELEMS ((size_t)B_ * L_)

#define DELTA   0.25f
#define CAPROW  49152
#define NSLICE  8
#define RLT     64

// ---- device scratch (no allocation allowed anywhere) ----
__device__ __align__(16) unsigned short g_zb[(size_t)B_ * D_ * L_];
__device__ __align__(16) unsigned short g_wb[(size_t)NE_ * D_];
__device__ float  g_sv1[2][B_ * LP];
__device__ float  g_sv2[2][B_ * LP];
__device__ int    g_si1[2][B_ * LP];
__device__ int    g_best[B_ * L_];
__device__ float  g_blog[B_ * L_];
__device__ float  g_zsqp[4][B_ * L_];
__device__ float  g_wsq[NE_];
__device__ int    g_flagcnt;
__device__ int    g_flaglist[CAPROW];
__device__ float  g_zg[(size_t)D_ * CAPROW];
__device__ float  g_rpv[NSLICE][CAPROW];
__device__ int    g_rpi[NSLICE][CAPROW];
__device__ double g_loss;

__device__ __forceinline__ uint32_t smem_u32(const void* p) {
    uint32_t a;
    asm("{ .reg .u64 t; cvta.to.shared.u64 t, %1; cvt.u32.u64 %0, t; }" : "=r"(a) : "l"(p));
    return a;
}
__device__ __forceinline__ unsigned short f2bf(float f) {   // RN-even
    uint32_t u = __float_as_uint(f);
    return (unsigned short)((u + 0x7FFFu + ((u >> 16) & 1u)) >> 16);
}

#define MMA_BF16(d, a, bb)                                                     \
    asm volatile("mma.sync.aligned.m16n8k16.row.col.f32.bf16.bf16.f32 "        \
        "{%0,%1,%2,%3}, {%4,%5,%6,%7}, {%8,%9}, {%0,%1,%2,%3};"                \
        : "+f"((d)[0]), "+f"((d)[1]), "+f"((d)[2]), "+f"((d)[3])               \
        : "r"((a)[0]), "r"((a)[1]), "r"((a)[2]), "r"((a)[3]),                  \
          "r"((bb)[0]), "r"((bb)[1]))

#define LDMX4(r, addr)                                                         \
    asm volatile("ldmatrix.sync.aligned.m8n8.x4.shared.b16 {%0,%1,%2,%3}, [%4];" \
        : "=r"((r)[0]), "=r"((r)[1]), "=r"((r)[2]), "=r"((r)[3]) : "r"(addr))

#define LDMX4T(r, addr)                                                        \
    asm volatile("ldmatrix.sync.aligned.m8n8.x4.trans.shared.b16 {%0,%1,%2,%3}, [%4];" \
        : "=r"((r)[0]), "=r"((r)[1]), "=r"((r)[2]), "=r"((r)[3]) : "r"(addr))

// ---- finalize ----
__global__ void finalize_kernel(float* __restrict__ out) {
    out[ZQ_ELEMS + IND_ELEMS] = (float)(2.25 * g_loss / ((double)B_ * D_ * L_));
}

// W -> bf16 + per-code sum of squares; block 0 resets run-state
__global__ void __launch_bounds__(128)
convert_w_kernel(const float* __restrict__ W) {
    __shared__ float red[4];
    const int n = blockIdx.x, tid = threadIdx.x;
    if (n == 0 && tid == 0) { g_flagcnt = 0; g_loss = 0.0; }
    const size_t base = (size_t)n * D_ + tid * 4;
    float4 v = *reinterpret_cast<const float4*>(W + base);
    uint2 o;
    o.x = (uint32_t)f2bf(v.x) | ((uint32_t)f2bf(v.y) << 16);
    o.y = (uint32_t)f2bf(v.z) | ((uint32_t)f2bf(v.w) << 16);
    *reinterpret_cast<uint2*>(g_wb + base) = o;
    float s = v.x * v.x + v.y * v.y + v.z * v.z + v.w * v.w;
    #pragma unroll
    for (int off = 16; off > 0; off >>= 1) s += __shfl_xor_sync(~0u, s, off);
    if ((tid & 31) == 0) red[tid >> 5] = s;
    __syncthreads();
    if (tid == 0) g_wsq[n] = red[0] + red[1] + red[2] + red[3];
}

// z -> bf16 + zsq partials: d split in 4 chunks (blockIdx.z), 2 cols/thread
__global__ void __launch_bounds__(128)
convert_z_kernel(const float* __restrict__ z) {
    const int tid = threadIdx.x;
    const int b = blockIdx.y, col = blockIdx.x * 256 + tid * 2;
    const int dz = blockIdx.z, d0 = dz * 128;
    const bool valid = col < L_;            // L even -> pair co-valid
    const float* zp = z + (size_t)b * D_ * L_ + col;
    unsigned short* zo = g_zb + (size_t)b * D_ * L_ + col;
    float acc0 = 0.0f, acc1 = 0.0f;
    #pragma unroll 8
    for (int dd = 0; dd < 128; ++dd) {
        const int d = d0 + dd;
        float2 v = valid ? *reinterpret_cast<const float2*>(&zp[(size_t)d * L_])
                         : make_float2(0.f, 0.f);
        if (valid)
            *reinterpret_cast<uint32_t*>(&zo[(size_t)d * L_]) =
                (uint32_t)f2bf(v.x) | ((uint32_t)f2bf(v.y) << 16);
        acc0 = fmaf(v.x, v.x, acc0);
        acc1 = fmaf(v.y, v.y, acc1);
    }
    if (valid) {
        g_zsqp[dz][b * L_ + col]     = acc0;
        g_zsqp[dz][b * L_ + col + 1] = acc1;
    }
}

// =====================================================================
// Screen half (byte-identical to the 379us round-12 version)
// =====================================================================
#define AST   18432            // 128 * 144
#define BST   17408            // 64 * 272
#define BOFF  (3 * AST)
#define EOFF  (3 * (AST + BST))
#define SMEM_SCREEN (EOFF + 4608)

__device__ __forceinline__ void screen_issue(
    const unsigned short* __restrict__ zrow,
    uint32_t sbase, int t, int tid, int lb, int halfrow)
{
    const int nsup = t >> 3;
    const int kb = (t & 7) * 64;
    const int st = t % 3;
    #pragma unroll
    for (int i = 0; i < 4; ++i) {            // A: 128 rows x 8 chunks(16B)
        int v = tid + i * 256;
        int row = v >> 3, ch = v & 7;
        uint32_t dst = sbase + st * AST + row * 144 + ch * 16;
        const unsigned short* src =
            g_wb + (size_t)(halfrow + nsup * 128 + row) * D_ + kb + ch * 8;
        asm volatile("cp.async.cg.shared.global [%0], [%1], 16;"
                     :: "r"(dst), "l"(src) : "memory");
    }
    #pragma unroll
    for (int i = 0; i < 4; ++i) {            // B: 64 k-rows x 16 chunks
        int v = tid + i * 256;
        int kr = v >> 4, ch = v & 15;
        uint32_t dst = sbase + BOFF + st * BST + kr * 272 + ch * 16;
        const unsigned short* src = zrow + (size_t)(kb + kr) * L_ + lb + ch * 8;
        uint32_t ssz = (lb + ch * 8 < L_) ? 16u : 0u;
        asm volatile("cp.async.cg.shared.global [%0], [%1], 16, %2;"
                     :: "r"(dst), "l"(src), "r"(ssz) : "memory");
    }
    asm volatile("cp.async.commit_group;" ::: "memory");
}

__global__ void __launch_bounds__(256, 2)
screen_kernel()
{
    extern __shared__ char smc[];
    const uint32_t sbase = smem_u32(smc);
    float* ep  = (float*)(smc + EOFF);
    float* wv1 = ep;                 // [2][128]
    float* wv2 = ep + 256;
    int*   wi1 = (int*)(ep + 512);
    float* rv1 = ep + 768;
    float* rv2 = ep + 896;
    int*   ri1 = (int*)(ep + 1024);

    const int tid = threadIdx.x, lane = tid & 31, w = tid >> 5;
    const int mw = w >> 2, nw = w & 3;
    const int g = lane >> 2, cth = lane & 3;
    const int b = blockIdx.y, lb = blockIdx.x * 128;
    const int half = blockIdx.z;
    const int halfrow = half * 512;
    const unsigned short* zrow = g_zb + (size_t)b * D_ * L_;

    if (tid < 128) { rv1[tid] = -3.0e38f; rv2[tid] = -3.0e38f; ri1[tid] = 0; }

    const uint32_t offA  = (uint32_t)((lane & 15) * 144 + (lane >> 4) * 16);
    const uint32_t offB4 = (uint32_t)((lane & 15) * 272 + (lane >> 4) * 16);

    float c[4][4][4];

    screen_issue(zrow, sbase, 0, tid, lb, halfrow);
    screen_issue(zrow, sbase, 1, tid, lb, halfrow);

    for (int t = 0; t < 32; ++t) {
        const int kc = t & 7, nsup = t >> 3, st = t % 3;

        if (t < 30) asm volatile("cp.async.wait_group 1;" ::: "memory");
        else        asm volatile("cp.async.wait_group 0;" ::: "memory");
        __syncthreads();
        if (t < 30) screen_issue(zrow, sbase, t + 2, tid, lb, halfrow);

        if (kc == 0) {
            #pragma unroll
            for (int mt = 0; mt < 4; ++mt)
                #pragma unroll
                for (int nt = 0; nt < 4; ++nt)
                    #pragma unroll
                    for (int r = 0; r < 4; ++r) c[mt][nt][r] = 0.0f;
        }

        const uint32_t aB = sbase + st * AST;
        const uint32_t bB = sbase + BOFF + st * BST;
        #pragma unroll
        for (int q = 0; q < 4; ++q) {
            uint32_t af[4][4], bq[2][4];
            #pragma unroll
            for (int mt = 0; mt < 4; ++mt)
                LDMX4(af[mt], aB + (uint32_t)((mw * 64 + mt * 16) * 144 + q * 32) + offA);
            #pragma unroll
            for (int ntp = 0; ntp < 2; ++ntp)
                LDMX4T(bq[ntp], bB + (uint32_t)(q * 16 * 272 + nw * 64 + ntp * 32) + offB4);
            #pragma unroll
            for (int mt = 0; mt < 4; ++mt)
                #pragma unroll
                for (int nt = 0; nt < 4; ++nt)
                    MMA_BF16(c[mt][nt], af[mt], &bq[nt >> 1][(nt & 1) * 2]);
        }

        if (kc == 7) {
            // ---- supertile epilogue: per-column top-2 ----
            #pragma unroll
            for (int nt = 0; nt < 4; ++nt) {
                #pragma unroll
                for (int p = 0; p < 2; ++p) {
                    float v1 = -3.0e38f, v2 = -3.0e38f; int i1 = 0;
                    #pragma unroll
                    for (int mt = 0; mt < 4; ++mt)
                        #pragma unroll
                        for (int r = 0; r < 2; ++r) {
                            float v = c[mt][nt][r * 2 + p];
                            int code = halfrow + nsup * 128 + mw * 64 + mt * 16 + r * 8 + g;
                            if (v > v1) { v2 = v1; v1 = v; i1 = code; }
                            else if (v > v2) v2 = v;
                        }
                    #pragma unroll
                    for (int off = 4; off < 32; off <<= 1) {
                        float ov1 = __shfl_xor_sync(~0u, v1, off);
                        float ov2 = __shfl_xor_sync(~0u, v2, off);
                        int   oi1 = __shfl_xor_sync(~0u, i1, off);
                        if (ov1 > v1) { v2 = fmaxf(v1, ov2); v1 = ov1; i1 = oi1; }
                        else          { v2 = fmaxf(v2, ov1); }
                    }
                    if (g == 0) {
                        int col = nw * 32 + nt * 8 + 2 * cth + p;
                        wv1[mw * 128 + col] = v1;
                        wv2[mw * 128 + col] = v2;
                        wi1[mw * 128 + col] = i1;
                    }
                }
            }
            __syncthreads();
            if (tid < 128) {
                float a1 = wv1[tid], a2 = wv2[tid];             int ai = wi1[tid];
                float b1 = wv1[128 + tid], b2 = wv2[128 + tid]; int bi = wi1[128 + tid];
                float m1, m2; int mi;
                if (a1 >= b1) { m1 = a1; mi = ai; m2 = fmaxf(a2, b1); }
                else          { m1 = b1; mi = bi; m2 = fmaxf(b2, a1); }
                if (m1 > rv1[tid]) {
                    rv2[tid] = fmaxf(rv1[tid], m2);
                    rv1[tid] = m1; ri1[tid] = mi;
                } else {
                    rv2[tid] = fmaxf(rv2[tid], m1);
                }
            }
            __syncthreads();
        }
    }

    if (tid < 128) {
        int idx = b * LP + lb + tid;
        g_sv1[half][idx] = rv1[tid];
        g_sv2[half][idx] = rv2[tid];
        g_si1[half][idx] = ri1[tid];
    }
}

// ---- merge halves, flag narrow margins, accumulate confident loss ----
__global__ void __launch_bounds__(256)
select_kernel()
{
    __shared__ double red[256];
    const int tid = threadIdx.x;
    double lsum = 0.0;
    for (int s = blockIdx.x * blockDim.x + tid; s < B_ * L_;
         s += gridDim.x * blockDim.x) {
        int b = s / L_, l = s % L_;
        int pidx = b * LP + l;
        float a1 = g_sv1[0][pidx], a2 = g_sv2[0][pidx]; int ai = g_si1[0][pidx];
        float b1 = g_sv1[1][pidx], b2 = g_sv2[1][pidx]; int bi = g_si1[1][pidx];
        float m1, m2; int mi;
        if (a1 >= b1) { m1 = a1; mi = ai; m2 = fmaxf(a2, b1); }
        else          { m1 = b1; mi = bi; m2 = fmaxf(b2, a1); }
        g_best[s] = mi;
        g_blog[s] = m1;
        if (m1 - m2 < DELTA) {
            int fs = atomicAdd(&g_flagcnt, 1);
            g_flaglist[fs] = (b << 16) | l;
        } else {
            float zsq = (g_zsqp[0][s] + g_zsqp[1][s])
                      + (g_zsqp[2][s] + g_zsqp[3][s]);
            lsum += (double)g_wsq[mi] - 2.0 * (double)m1 + (double)zsq;
        }
    }
    red[tid] = lsum;
    __syncthreads();
    #pragma unroll
    for (int s = 128; s > 0; s >>= 1) {
        if (tid < s) red[tid] += red[tid + s];
        __syncthreads();
    }
    if (tid == 0) atomicAdd(&g_loss, red[0]);
}

// ---- gather flagged z columns into compact k-major matrix ----
__global__ void __launch_bounds__(256)
gather_kernel(const float* __restrict__ z)
{
    const int cnt = g_flagcnt;
    const int tid = threadIdx.x;
    for (int slot = blockIdx.x; slot < cnt; slot += gridDim.x) {
        int meta = g_flaglist[slot];
        int b = meta >> 16, l = meta & 0xFFFF;
        g_zg[(size_t)tid * CAPROW + slot] = z[((size_t)b * D_ + tid) * L_ + l];
        g_zg[(size_t)(tid + 256) * CAPROW + slot] =
            z[((size_t)b * D_ + tid + 256) * L_ + l];
    }
}

// ---- exact fp32 rescan of flagged columns ----
__global__ void __launch_bounds__(256)
rescan_kernel(const float* __restrict__ W)
{
    __shared__ float Ws[32][128];
    __shared__ float Zs[32][RLT];
    __shared__ float pv[32][RLT];
    __shared__ int   pi[32][RLT];

    const int tid = threadIdx.x;
    const int tx = tid & 7, ty = tid >> 3;
    const int cnt = g_flagcnt;
    const int tiles = (cnt + RLT - 1) / RLT;

    for (int item = blockIdx.x; item < tiles * NSLICE; item += gridDim.x) {
        const int ct = item / NSLICE, ns = item % NSLICE;
        const int cb = ct * RLT, nb = ns * 128;

        float acc[4][8];
        #pragma unroll
        for (int i = 0; i < 4; ++i)
            #pragma unroll
            for (int j = 0; j < 8; ++j) acc[i][j] = 0.0f;

        for (int kc = 0; kc < 16; ++kc) {
            const int kb = kc * 32;
            __syncthreads();
            #pragma unroll
            for (int p = 0; p < 4; ++p) {
                int v = tid + p * 256;
                int n = v >> 3, kq = v & 7;
                float4 wv = *reinterpret_cast<const float4*>(
                    &W[(size_t)(nb + n) * D_ + kb + kq * 4]);
                Ws[kq * 4 + 0][n] = wv.x;
                Ws[kq * 4 + 1][n] = wv.y;
                Ws[kq * 4 + 2][n] = wv.z;
                Ws[kq * 4 + 3][n] = wv.w;
            }
            #pragma unroll
            for (int p = 0; p < 2; ++p) {
                int v = tid + p * 256;
                int kr = v >> 4, cq = v & 15;
                float4 zv = *reinterpret_cast<const float4*>(
                    &g_zg[(size_t)(kb + kr) * CAPROW + cb + cq * 4]);
                *reinterpret_cast<float4*>(&Zs[kr][cq * 4]) = zv;
            }
            __syncthreads();
            #pragma unroll
            for (int k = 0; k < 32; ++k) {
                float4 wa = *reinterpret_cast<const float4*>(&Ws[k][ty * 4]);
                float4 za = *reinterpret_cast<const float4*>(&Zs[k][tx * 8]);
                float4 zc = *reinterpret_cast<const float4*>(&Zs[k][tx * 8 + 4]);
                float wf[4] = {wa.x, wa.y, wa.z, wa.w};
                float zf[8] = {za.x, za.y, za.z, za.w, zc.x, zc.y, zc.z, zc.w};
                #pragma unroll
                for (int i = 0; i < 4; ++i)
                    #pragma unroll
                    for (int j = 0; j < 8; ++j)
                        acc[i][j] = fmaf(wf[i], zf[j], acc[i][j]);
            }
        }
        __syncthreads();
        #pragma unroll
        for (int j = 0; j < 8; ++j) {
            float m = acc[0][j];
            int mi = nb + ty * 4;
            #pragma unroll
            for (int i = 1; i < 4; ++i) {
                float v = acc[i][j];
                if (v > m) { m = v; mi = nb + ty * 4 + i; }
            }
            pv[ty][tx * 8 + j] = m;
            pi[ty][tx * 8 + j] = mi;
        }
        __syncthreads();
        if (tid < RLT) {
            float m = pv[0][tid]; int mi = pi[0][tid];
            #pragma unroll
            for (int r = 1; r < 32; ++r) {
                float v = pv[r][tid]; int vi = pi[r][tid];
                if (v > m || (v == m && vi < mi)) { m = v; mi = vi; }
            }
            g_rpv[ns][cb + tid] = m;
            g_rpi[ns][cb + tid] = mi;
        }
        __syncthreads();
    }
}

// ---- flagged columns: fold slices, write best, accumulate flagged loss ----
__global__ void __launch_bounds__(256)
flagmerge_kernel()
{
    __shared__ double red[256];
    const int tid = threadIdx.x;
    const int cnt = g_flagcnt;
    double lsum = 0.0;
    for (int s = blockIdx.x * blockDim.x + tid; s < cnt;
         s += gridDim.x * blockDim.x) {
        float bv = g_rpv[0][s]; int bi = g_rpi[0][s];
        #pragma unroll
        for (int r = 1; r < NSLICE; ++r) {
            float v = g_rpv[r][s];
            if (v > bv) { bv = v; bi = g_rpi[r][s]; }
        }
        int meta = g_flaglist[s];
        int bl = (meta >> 16) * L_ + (meta & 0xFFFF);
        g_best[bl] = bi;
        g_blog[bl] = bv;
        float zsq = (g_zsqp[0][bl] + g_zsqp[1][bl])
                  + (g_zsqp[2][bl] + g_zsqp[3][bl]);
        lsum += (double)g_wsq[bi] - 2.0 * (double)bv + (double)zsq;
    }
    red[tid] = lsum;
    __syncthreads();
    #pragma unroll
    for (int s = 128; s > 0; s >>= 1) {
        if (tid < s) red[tid] += red[tid + s];
        __syncthreads();
    }
    if (tid == 0) atomicAdd(&g_loss, red[0]);
}

// ---- output: ind + z_q gather; d split across blockIdx.y (8x CTAs) ----
#define OW_SMEM (256 * 65 * 4)
__global__ void __launch_bounds__(256)
output_kernel(const float* __restrict__ W, float* __restrict__ out)
{
    extern __shared__ float sw[];          // [256][65]
    __shared__ int besti[256];
    const int tid = threadIdx.x, lane = tid & 31, w = tid >> 5;
    const int b = blockIdx.x / 12, lt = blockIdx.x % 12;
    const int d0 = blockIdx.y * 64;
    const int lbase = lt * 256;
    const int valid = (L_ - lbase < 256) ? (L_ - lbase) : 256;

    {
        int bi = 0;
        if (tid < valid) {
            bi = g_best[b * L_ + lbase + tid];
            if (blockIdx.y == 0)
                out[ZQ_ELEMS + (size_t)b * L_ + lbase + tid] = (float)bi;
        }
        besti[tid] = bi;
    }
    __syncthreads();

    #pragma unroll
    for (int cs = 0; cs < 32; ++cs) {
        int col = w * 32 + cs;
        const float2 wv = *reinterpret_cast<const float2*>(
            &W[(size_t)besti[col] * D_ + d0 + lane * 2]);
        sw[col * 65 + lane * 2]     = wv.x;
        sw[col * 65 + lane * 2 + 1] = wv.y;
    }
    __syncthreads();
    #pragma unroll 8
    for (int it = 0; it < 64; ++it) {
        int idx = it * 256 + tid;
        int col = idx & 255;
        int dl = idx >> 8;
        if (col < valid) {
            out[((size_t)b * D_ + d0 + dl) * L_ + lbase + col] =
                sw[col * 65 + dl];
        }
    }
}

extern "C" void kernel_launch(void* const* d_in, const int* in_sizes, int n_in,
                              void* d_out, int out_size) {
    const float* z = (const float*)d_in[0];
    const float* W = (const float*)d_in[1];
    if (n_in >= 2 && in_sizes[0] == NE_ * D_) {
        z = (const float*)d_in[1];
        W = (const float*)d_in[0];
    }
    float* out = (float*)d_out;

    cudaFuncSetAttribute(screen_kernel,
                         cudaFuncAttributeMaxDynamicSharedMemorySize, SMEM_SCREEN);
    cudaFuncSetAttribute(output_kernel,
                         cudaFuncAttributeMaxDynamicSharedMemorySize, OW_SMEM);

    convert_w_kernel<<<NE_, 128>>>(W);
    {
        dim3 grd((L_ + 255) / 256, B_, 4);
        convert_z_kernel<<<grd, 128>>>(z);
    }
    {
        dim3 grd((L_ + 127) / 128, B_, 2);
        screen_kernel<<<grd, 256, SMEM_SCREEN>>>();
    }
    select_kernel<<<96, 256>>>();
    gather_kernel<<<512, 256>>>(z);
    rescan_kernel<<<512, 256>>>(W);
    flagmerge_kernel<<<64, 256>>>();
    {
        dim3 grd(B_ * 12, 8);
        output_kernel<<<grd, 256, OW_SMEM>>>(W, out);
    }
    finalize_kernel<<<1, 1>>>(out);
}

// round 15
// speedup vs baseline: 1.4837x; 1.4837x over previous
#include <cuda_runtime.h>
#include <cstdint>

#define B_    16
#define D_    512
#define L_    3000
#define NE_   1024
#define LP    3072
#define ZQ_ELEMS  ((size_t)B_ * D_ * L_)
#define IND_ELEMS ((size_t)B_ * L_)

#define DELTA   0.25f
#define CAPROW  49152
#define NSLICE  8
#define RLT     64

// ---- device scratch (no allocation allowed anywhere) ----
__device__ __align__(16) unsigned short g_zb[(size_t)B_ * D_ * L_];
__device__ __align__(16) unsigned short g_wb[(size_t)NE_ * D_];
__device__ float  g_sv1[2][B_ * LP];
__device__ float  g_sv2[2][B_ * LP];
__device__ int    g_si1[2][B_ * LP];
__device__ int    g_best[B_ * L_];
__device__ float  g_blog[B_ * L_];
__device__ float  g_zsqp[4][B_ * L_];
__device__ float  g_wsq[NE_];
__device__ int    g_flagcnt;
__device__ int    g_flaglist[CAPROW];
__device__ float  g_zg[(size_t)D_ * CAPROW];
__device__ float  g_rpv[NSLICE][CAPROW];
__device__ int    g_rpi[NSLICE][CAPROW];
__device__ double g_loss;

__device__ __forceinline__ uint32_t smem_u32(const void* p) {
    uint32_t a;
    asm("{ .reg .u64 t; cvta.to.shared.u64 t, %1; cvt.u32.u64 %0, t; }" : "=r"(a) : "l"(p));
    return a;
}
__device__ __forceinline__ unsigned short f2bf(float f) {   // RN-even
    uint32_t u = __float_as_uint(f);
    return (unsigned short)((u + 0x7FFFu + ((u >> 16) & 1u)) >> 16);
}

#define MMA_BF16(d, a, bb)                                                     \
    asm volatile("mma.sync.aligned.m16n8k16.row.col.f32.bf16.bf16.f32 "        \
        "{%0,%1,%2,%3}, {%4,%5,%6,%7}, {%8,%9}, {%0,%1,%2,%3};"                \
        : "+f"((d)[0]), "+f"((d)[1]), "+f"((d)[2]), "+f"((d)[3])               \
        : "r"((a)[0]), "r"((a)[1]), "r"((a)[2]), "r"((a)[3]),                  \
          "r"((bb)[0]), "r"((bb)[1]))

#define LDMX4(r, addr)                                                         \
    asm volatile("ldmatrix.sync.aligned.m8n8.x4.shared.b16 {%0,%1,%2,%3}, [%4];" \
        : "=r"((r)[0]), "=r"((r)[1]), "=r"((r)[2]), "=r"((r)[3]) : "r"(addr))

// x4.trans: lanes 0-15 -> k0..15 of n8 block at base col; lanes 16-31 ->
// k0..15 of n8 block at base col + 16B. Yields TWO B fragments per instr.
#define LDMX4T(r, addr)                                                        \
    asm volatile("ldmatrix.sync.aligned.m8n8.x4.trans.shared.b16 {%0,%1,%2,%3}, [%4];" \
        : "=r"((r)[0]), "=r"((r)[1]), "=r"((r)[2]), "=r"((r)[3]) : "r"(addr))

// ---- small kernels ----
__global__ void init_kernel() { g_loss = 0.0; g_flagcnt = 0; }

__global__ void finalize_kernel(float* __restrict__ out) {
    out[ZQ_ELEMS + IND_ELEMS] = (float)(2.25 * g_loss / ((double)B_ * D_ * L_));
}

// W -> bf16 + per-code sum of squares
__global__ void __launch_bounds__(128)
convert_w_kernel(const float* __restrict__ W) {
    __shared__ float red[4];
    const int n = blockIdx.x, tid = threadIdx.x;
    const size_t base = (size_t)n * D_ + tid * 4;
    float4 v = *reinterpret_cast<const float4*>(W + base);
    uint2 o;
    o.x = (uint32_t)f2bf(v.x) | ((uint32_t)f2bf(v.y) << 16);
    o.y = (uint32_t)f2bf(v.z) | ((uint32_t)f2bf(v.w) << 16);
    *reinterpret_cast<uint2*>(g_wb + base) = o;
    float s = v.x * v.x + v.y * v.y + v.z * v.z + v.w * v.w;
    #pragma unroll
    for (int off = 16; off > 0; off >>= 1) s += __shfl_xor_sync(~0u, s, off);
    if ((tid & 31) == 0) red[tid >> 5] = s;
    __syncthreads();
    if (tid == 0) g_wsq[n] = red[0] + red[1] + red[2] + red[3];
}

// z -> bf16 + zsq partials: d split in 4 chunks (blockIdx.z), 2 cols/thread
__global__ void __launch_bounds__(128)
convert_z_kernel(const float* __restrict__ z) {
    const int tid = threadIdx.x;
    const int b = blockIdx.y, col = blockIdx.x * 256 + tid * 2;
    const int dz = blockIdx.z, d0 = dz * 128;
    const bool valid = col < L_;            // L even -> pair co-valid
    const float* zp = z + (size_t)b * D_ * L_ + col;
    unsigned short* zo = g_zb + (size_t)b * D_ * L_ + col;
    float acc0 = 0.0f, acc1 = 0.0f;
    #pragma unroll 8
    for (int dd = 0; dd < 128; ++dd) {
        const int d = d0 + dd;
        float2 v = valid ? *reinterpret_cast<const float2*>(&zp[(size_t)d * L_])
                         : make_float2(0.f, 0.f);
        if (valid)
            *reinterpret_cast<uint32_t*>(&zo[(size_t)d * L_]) =
                (uint32_t)f2bf(v.x) | ((uint32_t)f2bf(v.y) << 16);
        acc0 = fmaf(v.x, v.x, acc0);
        acc1 = fmaf(v.y, v.y, acc1);
    }
    if (valid) {
        g_zsqp[dz][b * L_ + col]     = acc0;
        g_zsqp[dz][b * L_ + col + 1] = acc1;
    }
}

// =====================================================================
// Screen half: 512 codes (4 supertiles) x 128 cols; bf16 mma m16n8k16;
// K-chunk 64, 3-stage cp.async ring, one __syncthreads per k-iter.
// B fragments via ldmatrix.x4.trans (2 frags/instr) -> LDSM 8->6 per k16.
// =====================================================================
#define AST   18432            // 128 * 144
#define BST   17408            // 64 * 272
#define BOFF  (3 * AST)
#define EOFF  (3 * (AST + BST))
#define SMEM_SCREEN (EOFF + 4608)

__device__ __forceinline__ void screen_issue(
    const unsigned short* __restrict__ zrow,
    uint32_t sbase, int t, int tid, int lb, int halfrow)
{
    const int nsup = t >> 3;
    const int kb = (t & 7) * 64;
    const int st = t % 3;
    #pragma unroll
    for (int i = 0; i < 4; ++i) {            // A: 128 rows x 8 chunks(16B)
        int v = tid + i * 256;
        int row = v >> 3, ch = v & 7;
        uint32_t dst = sbase + st * AST + row * 144 + ch * 16;
        const unsigned short* src =
            g_wb + (size_t)(halfrow + nsup * 128 + row) * D_ + kb + ch * 8;
        asm volatile("cp.async.cg.shared.global [%0], [%1], 16;"
                     :: "r"(dst), "l"(src) : "memory");
    }
    #pragma unroll
    for (int i = 0; i < 4; ++i) {            // B: 64 k-rows x 16 chunks
        int v = tid + i * 256;
        int kr = v >> 4, ch = v & 15;
        uint32_t dst = sbase + BOFF + st * BST + kr * 272 + ch * 16;
        const unsigned short* src = zrow + (size_t)(kb + kr) * L_ + lb + ch * 8;
        uint32_t ssz = (lb + ch * 8 < L_) ? 16u : 0u;
        asm volatile("cp.async.cg.shared.global [%0], [%1], 16, %2;"
                     :: "r"(dst), "l"(src), "r"(ssz) : "memory");
    }
    asm volatile("cp.async.commit_group;" ::: "memory");
}

__global__ void __launch_bounds__(256, 2)
screen_kernel()
{
    extern __shared__ char smc[];
    const uint32_t sbase = smem_u32(smc);
    float* ep  = (float*)(smc + EOFF);
    float* wv1 = ep;                 // [2][128]
    float* wv2 = ep + 256;
    int*   wi1 = (int*)(ep + 512);
    float* rv1 = ep + 768;
    float* rv2 = ep + 896;
    int*   ri1 = (int*)(ep + 1024);

    const int tid = threadIdx.x, lane = tid & 31, w = tid >> 5;
    const int mw = w >> 2, nw = w & 3;
    const int g = lane >> 2, cth = lane & 3;
    const int b = blockIdx.y, lb = blockIdx.x * 128;
    const int half = blockIdx.z;
    const int halfrow = half * 512;
    const unsigned short* zrow = g_zb + (size_t)b * D_ * L_;

    if (tid < 128) { rv1[tid] = -3.0e38f; rv2[tid] = -3.0e38f; ri1[tid] = 0; }

    const uint32_t offA  = (uint32_t)((lane & 15) * 144 + (lane >> 4) * 16);
    const uint32_t offB4 = (uint32_t)((lane & 15) * 272 + (lane >> 4) * 16);

    float c[4][4][4];

    screen_issue(zrow, sbase, 0, tid, lb, halfrow);
    screen_issue(zrow, sbase, 1, tid, lb, halfrow);

    for (int t = 0; t < 32; ++t) {
        const int kc = t & 7, nsup = t >> 3, st = t % 3;

        if (t < 30) asm volatile("cp.async.wait_group 1;" ::: "memory");
        else        asm volatile("cp.async.wait_group 0;" ::: "memory");
        __syncthreads();
        if (t < 30) screen_issue(zrow, sbase, t + 2, tid, lb, halfrow);

        if (kc == 0) {
            #pragma unroll
            for (int mt = 0; mt < 4; ++mt)
                #pragma unroll
                for (int nt = 0; nt < 4; ++nt)
                    #pragma unroll
                    for (int r = 0; r < 4; ++r) c[mt][nt][r] = 0.0f;
        }

        const uint32_t aB = sbase + st * AST;
        const uint32_t bB = sbase + BOFF + st * BST;
        #pragma unroll
        for (int q = 0; q < 4; ++q) {
            uint32_t af[4][4], bq[2][4];
            #pragma unroll
            for (int mt = 0; mt < 4; ++mt)
                LDMX4(af[mt], aB + (uint32_t)((mw * 64 + mt * 16) * 144 + q * 32) + offA);
            #pragma unroll
            for (int ntp = 0; ntp < 2; ++ntp)
                LDMX4T(bq[ntp], bB + (uint32_t)(q * 16 * 272 + nw * 64 + ntp * 32) + offB4);
            #pragma unroll
            for (int mt = 0; mt < 4; ++mt)
                #pragma unroll
                for (int nt = 0; nt < 4; ++nt)
                    MMA_BF16(c[mt][nt], af[mt], &bq[nt >> 1][(nt & 1) * 2]);
        }

        if (kc == 7) {
            // ---- supertile epilogue: per-column top-2 ----
            #pragma unroll
            for (int nt = 0; nt < 4; ++nt) {
                #pragma unroll
                for (int p = 0; p < 2; ++p) {
                    float v1 = -3.0e38f, v2 = -3.0e38f; int i1 = 0;
                    #pragma unroll
                    for (int mt = 0; mt < 4; ++mt)
                        #pragma unroll
                        for (int r = 0; r < 2; ++r) {
                            float v = c[mt][nt][r * 2 + p];
                            int code = halfrow + nsup * 128 + mw * 64 + mt * 16 + r * 8 + g;
                            if (v > v1) { v2 = v1; v1 = v; i1 = code; }
                            else if (v > v2) v2 = v;
                        }
                    #pragma unroll
                    for (int off = 4; off < 32; off <<= 1) {
                        float ov1 = __shfl_xor_sync(~0u, v1, off);
                        float ov2 = __shfl_xor_sync(~0u, v2, off);
                        int   oi1 = __shfl_xor_sync(~0u, i1, off);
                        if (ov1 > v1) { v2 = fmaxf(v1, ov2); v1 = ov1; i1 = oi1; }
                        else          { v2 = fmaxf(v2, ov1); }
                    }
                    if (g == 0) {
                        int col = nw * 32 + nt * 8 + 2 * cth + p;
                        wv1[mw * 128 + col] = v1;
                        wv2[mw * 128 + col] = v2;
                        wi1[mw * 128 + col] = i1;
                    }
                }
            }
            __syncthreads();
            if (tid < 128) {
                float a1 = wv1[tid], a2 = wv2[tid];             int ai = wi1[tid];
                float b1 = wv1[128 + tid], b2 = wv2[128 + tid]; int bi = wi1[128 + tid];
                float m1, m2; int mi;
                if (a1 >= b1) { m1 = a1; mi = ai; m2 = fmaxf(a2, b1); }
                else          { m1 = b1; mi = bi; m2 = fmaxf(b2, a1); }
                if (m1 > rv1[tid]) {
                    rv2[tid] = fmaxf(rv1[tid], m2);
                    rv1[tid] = m1; ri1[tid] = mi;
                } else {
                    rv2[tid] = fmaxf(rv2[tid], m1);
                }
            }
            __syncthreads();
        }
    }

    if (tid < 128) {
        int idx = b * LP + lb + tid;
        g_sv1[half][idx] = rv1[tid];
        g_sv2[half][idx] = rv2[tid];
        g_si1[half][idx] = ri1[tid];
    }
}

// ---- merge halves, flag narrow margins ----
__global__ void __launch_bounds__(256)
select_kernel()
{
    for (int s = blockIdx.x * blockDim.x + threadIdx.x; s < B_ * L_;
         s += gridDim.x * blockDim.x) {
        int b = s / L_, l = s % L_;
        int pidx = b * LP + l;
        float a1 = g_sv1[0][pidx], a2 = g_sv2[0][pidx]; int ai = g_si1[0][pidx];
        float b1 = g_sv1[1][pidx], b2 = g_sv2[1][pidx]; int bi = g_si1[1][pidx];
        float m1, m2; int mi;
        if (a1 >= b1) { m1 = a1; mi = ai; m2 = fmaxf(a2, b1); }
        else          { m1 = b1; mi = bi; m2 = fmaxf(b2, a1); }
        g_best[s] = mi;
        g_blog[s] = m1;
        if (m1 - m2 < DELTA) {
            int fs = atomicAdd(&g_flagcnt, 1);
            g_flaglist[fs] = (b << 16) | l;
        }
    }
}

// ---- gather flagged z columns into compact k-major matrix ----
__global__ void __launch_bounds__(256)
gather_kernel(const float* __restrict__ z)
{
    const int cnt = g_flagcnt;
    const int tid = threadIdx.x;
    for (int slot = blockIdx.x; slot < cnt; slot += gridDim.x) {
        int meta = g_flaglist[slot];
        int b = meta >> 16, l = meta & 0xFFFF;
        g_zg[(size_t)tid * CAPROW + slot] = z[((size_t)b * D_ + tid) * L_ + l];
        g_zg[(size_t)(tid + 256) * CAPROW + slot] =
            z[((size_t)b * D_ + tid + 256) * L_ + l];
    }
}

// ---- exact fp32 rescan of flagged columns ----
__global__ void __launch_bounds__(256)
rescan_kernel(const float* __restrict__ W)
{
    __shared__ float Ws[32][128];
    __shared__ float Zs[32][RLT];
    __shared__ float pv[32][RLT];
    __shared__ int   pi[32][RLT];

    const int tid = threadIdx.x;
    const int tx = tid & 7, ty = tid >> 3;
    const int cnt = g_flagcnt;
    const int tiles = (cnt + RLT - 1) / RLT;

    for (int item = blockIdx.x; item < tiles * NSLICE; item += gridDim.x) {
        const int ct = item / NSLICE, ns = item % NSLICE;
        const int cb = ct * RLT, nb = ns * 128;

        float acc[4][8];
        #pragma unroll
        for (int i = 0; i < 4; ++i)
            #pragma unroll
            for (int j = 0; j < 8; ++j) acc[i][j] = 0.0f;

        for (int kc = 0; kc < 16; ++kc) {
            const int kb = kc * 32;
            __syncthreads();
            #pragma unroll
            for (int p = 0; p < 4; ++p) {
                int v = tid + p * 256;
                int n = v >> 3, kq = v & 7;
                float4 wv = *reinterpret_cast<const float4*>(
                    &W[(size_t)(nb + n) * D_ + kb + kq * 4]);
                Ws[kq * 4 + 0][n] = wv.x;
                Ws[kq * 4 + 1][n] = wv.y;
                Ws[kq * 4 + 2][n] = wv.z;
                Ws[kq * 4 + 3][n] = wv.w;
            }
            #pragma unroll
            for (int p = 0; p < 2; ++p) {
                int v = tid + p * 256;
                int kr = v >> 4, cq = v & 15;
                float4 zv = *reinterpret_cast<const float4*>(
                    &g_zg[(size_t)(kb + kr) * CAPROW + cb + cq * 4]);
                *reinterpret_cast<float4*>(&Zs[kr][cq * 4]) = zv;
            }
            __syncthreads();
            #pragma unroll
            for (int k = 0; k < 32; ++k) {
                float4 wa = *reinterpret_cast<const float4*>(&Ws[k][ty * 4]);
                float4 za = *reinterpret_cast<const float4*>(&Zs[k][tx * 8]);
                float4 zc = *reinterpret_cast<const float4*>(&Zs[k][tx * 8 + 4]);
                float wf[4] = {wa.x, wa.y, wa.z, wa.w};
                float zf[8] = {za.x, za.y, za.z, za.w, zc.x, zc.y, zc.z, zc.w};
                #pragma unroll
                for (int i = 0; i < 4; ++i)
                    #pragma unroll
                    for (int j = 0; j < 8; ++j)
                        acc[i][j] = fmaf(wf[i], zf[j], acc[i][j]);
            }
        }
        __syncthreads();
        #pragma unroll
        for (int j = 0; j < 8; ++j) {
            float m = acc[0][j];
            int mi = nb + ty * 4;
            #pragma unroll
            for (int i = 1; i < 4; ++i) {
                float v = acc[i][j];
                if (v > m) { m = v; mi = nb + ty * 4 + i; }
            }
            pv[ty][tx * 8 + j] = m;
            pi[ty][tx * 8 + j] = mi;
        }
        __syncthreads();
        if (tid < RLT) {
            float m = pv[0][tid]; int mi = pi[0][tid];
            #pragma unroll
            for (int r = 1; r < 32; ++r) {
                float v = pv[r][tid]; int vi = pi[r][tid];
                if (v > m || (v == m && vi < mi)) { m = v; mi = vi; }
            }
            g_rpv[ns][cb + tid] = m;
            g_rpi[ns][cb + tid] = mi;
        }
        __syncthreads();
    }
}

__global__ void __launch_bounds__(256)
flagmerge_kernel()
{
    const int cnt = g_flagcnt;
    for (int s = blockIdx.x * blockDim.x + threadIdx.x; s < cnt;
         s += gridDim.x * blockDim.x) {
        float bv = g_rpv[0][s]; int bi = g_rpi[0][s];
        #pragma unroll
        for (int r = 1; r < NSLICE; ++r) {
            float v = g_rpv[r][s];
            if (v > bv) { bv = v; bi = g_rpi[r][s]; }
        }
        int meta = g_flaglist[s];
        int bl = (meta >> 16) * L_ + (meta & 0xFFFF);
        g_best[bl] = bi;
        g_blog[bl] = bv;
    }
}

// ---- output: ind + z_q gather; d split across blockIdx.y (8x CTAs) ----
#define OW_SMEM (256 * 65 * 4)
__global__ void __launch_bounds__(256)
output_kernel(const float* __restrict__ W, float* __restrict__ out)
{
    extern __shared__ float sw[];          // [256][65]
    __shared__ int besti[256];
    const int tid = threadIdx.x, lane = tid & 31, w = tid >> 5;
    const int b = blockIdx.x / 12, lt = blockIdx.x % 12;
    const int d0 = blockIdx.y * 64;
    const int lbase = lt * 256;
    const int valid = (L_ - lbase < 256) ? (L_ - lbase) : 256;

    {
        int bi = 0;
        if (tid < valid) {
            bi = g_best[b * L_ + lbase + tid];
            if (blockIdx.y == 0)
                out[ZQ_ELEMS + (size_t)b * L_ + lbase + tid] = (float)bi;
        }
        besti[tid] = bi;
    }
    __syncthreads();

    #pragma unroll
    for (int cs = 0; cs < 32; ++cs) {
        int col = w * 32 + cs;
        const float2 wv = *reinterpret_cast<const float2*>(
            &W[(size_t)besti[col] * D_ + d0 + lane * 2]);
        sw[col * 65 + lane * 2]     = wv.x;
        sw[col * 65 + lane * 2 + 1] = wv.y;
    }
    __syncthreads();
    #pragma unroll 8
    for (int it = 0; it < 64; ++it) {
        int idx = it * 256 + tid;
        int col = idx & 255;
        int dl = idx >> 8;
        if (col < valid) {
            out[((size_t)b * D_ + d0 + dl) * L_ + lbase + col] =
                sw[col * 65 + dl];
        }
    }
}

// ---- loss via identity: wsq[ind] - 2*logit + sum(zsq partials) ----
__global__ void __launch_bounds__(256)
loss_kernel()
{
    __shared__ double red[256];
    const int tid = threadIdx.x;
    double lsum = 0.0;
    for (int s = blockIdx.x * blockDim.x + tid; s < B_ * L_;
         s += gridDim.x * blockDim.x) {
        float zsq = (g_zsqp[0][s] + g_zsqp[1][s]) + (g_zsqp[2][s] + g_zsqp[3][s]);
        lsum += (double)g_wsq[g_best[s]] - 2.0 * (double)g_blog[s] + (double)zsq;
    }
    red[tid] = lsum;
    __syncthreads();
    #pragma unroll
    for (int s = 128; s > 0; s >>= 1) {
        if (tid < s) red[tid] += red[tid + s];
        __syncthreads();
    }
    if (tid == 0) atomicAdd(&g_loss, red[0]);
}

extern "C" void kernel_launch(void* const* d_in, const int* in_sizes, int n_in,
                              void* d_out, int out_size) {
    const float* z = (const float*)d_in[0];
    const float* W = (const float*)d_in[1];
    if (n_in >= 2 && in_sizes[0] == NE_ * D_) {
        z = (const float*)d_in[1];
        W = (const float*)d_in[0];
    }
    float* out = (float*)d_out;

    cudaFuncSetAttribute(screen_kernel,
                         cudaFuncAttributeMaxDynamicSharedMemorySize, SMEM_SCREEN);
    cudaFuncSetAttribute(output_kernel,
                         cudaFuncAttributeMaxDynamicSharedMemorySize, OW_SMEM);

    init_kernel<<<1, 1>>>();
    convert_w_kernel<<<NE_, 128>>>(W);
    {
        dim3 grd((L_ + 255) / 256, B_, 4);
        convert_z_kernel<<<grd, 128>>>(z);
    }
    {
        dim3 grd((L_ + 127) / 128, B_, 2);
        screen_kernel<<<grd, 256, SMEM_SCREEN>>>();
    }
    select_kernel<<<96, 256>>>();
    gather_kernel<<<256, 256>>>(z);
    rescan_kernel<<<512, 256>>>(W);
    flagmerge_kernel<<<64, 256>>>();
    {
        dim3 grd(B_ * 12, 8);
        output_kernel<<<grd, 256, OW_SMEM>>>(W, out);
    }
    loss_kernel<<<96, 256>>>();
    finalize_kernel<<<1, 1>>>(out);
}

// round 16
// speedup vs baseline: 1.4974x; 1.0092x over previous
#include <cuda_runtime.h>
#include <cstdint>

#define B_    16
#define D_    512
#define L_    3000
#define NE_   1024
#define LP    3072
#define ZQ_ELEMS  ((size_t)B_ * D_ * L_)
#define IND_ELEMS ((size_t)B_ * L_)

#define DELTA   0.25f
#define CAPROW  49152
#define NSLICE  8
#define RLT     32

// ---- device scratch (no allocation allowed anywhere) ----
__device__ __align__(16) unsigned short g_zb[(size_t)B_ * D_ * L_];
__device__ __align__(16) unsigned short g_wb[(size_t)NE_ * D_];
__device__ float  g_sv1[2][B_ * LP];
__device__ float  g_sv2[2][B_ * LP];
__device__ int    g_si1[2][B_ * LP];
__device__ int    g_best[B_ * L_];
__device__ float  g_blog[B_ * L_];
__device__ float  g_zsqp[4][B_ * L_];
__device__ float  g_wsq[NE_];
__device__ int    g_flagcnt;
__device__ int    g_flaglist[CAPROW];
__device__ float  g_zg[(size_t)D_ * CAPROW];
__device__ float  g_rpv[NSLICE][CAPROW];
__device__ int    g_rpi[NSLICE][CAPROW];
__device__ double g_loss;

__device__ __forceinline__ uint32_t smem_u32(const void* p) {
    uint32_t a;
    asm("{ .reg .u64 t; cvta.to.shared.u64 t, %1; cvt.u32.u64 %0, t; }" : "=r"(a) : "l"(p));
    return a;
}
__device__ __forceinline__ unsigned short f2bf(float f) {   // RN-even
    uint32_t u = __float_as_uint(f);
    return (unsigned short)((u + 0x7FFFu + ((u >> 16) & 1u)) >> 16);
}

#define MMA_BF16(d, a, bb)                                                     \
    asm volatile("mma.sync.aligned.m16n8k16.row.col.f32.bf16.bf16.f32 "        \
        "{%0,%1,%2,%3}, {%4,%5,%6,%7}, {%8,%9}, {%0,%1,%2,%3};"                \
        : "+f"((d)[0]), "+f"((d)[1]), "+f"((d)[2]), "+f"((d)[3])               \
        : "r"((a)[0]), "r"((a)[1]), "r"((a)[2]), "r"((a)[3]),                  \
          "r"((bb)[0]), "r"((bb)[1]))

#define LDMX4(r, addr)                                                         \
    asm volatile("ldmatrix.sync.aligned.m8n8.x4.shared.b16 {%0,%1,%2,%3}, [%4];" \
        : "=r"((r)[0]), "=r"((r)[1]), "=r"((r)[2]), "=r"((r)[3]) : "r"(addr))

// x4.trans: lanes 0-15 -> k0..15 of n8 block at base col; lanes 16-31 ->
// k0..15 of n8 block at base col + 16B. Yields TWO B fragments per instr.
#define LDMX4T(r, addr)                                                        \
    asm volatile("ldmatrix.sync.aligned.m8n8.x4.trans.shared.b16 {%0,%1,%2,%3}, [%4];" \
        : "=r"((r)[0]), "=r"((r)[1]), "=r"((r)[2]), "=r"((r)[3]) : "r"(addr))

// ---- small kernels ----
__global__ void init_kernel() { g_loss = 0.0; g_flagcnt = 0; }

__global__ void finalize_kernel(float* __restrict__ out) {
    out[ZQ_ELEMS + IND_ELEMS] = (float)(2.25 * g_loss / ((double)B_ * D_ * L_));
}

// W -> bf16 + per-code sum of squares
__global__ void __launch_bounds__(128)
convert_w_kernel(const float* __restrict__ W) {
    __shared__ float red[4];
    const int n = blockIdx.x, tid = threadIdx.x;
    const size_t base = (size_t)n * D_ + tid * 4;
    float4 v = *reinterpret_cast<const float4*>(W + base);
    uint2 o;
    o.x = (uint32_t)f2bf(v.x) | ((uint32_t)f2bf(v.y) << 16);
    o.y = (uint32_t)f2bf(v.z) | ((uint32_t)f2bf(v.w) << 16);
    *reinterpret_cast<uint2*>(g_wb + base) = o;
    float s = v.x * v.x + v.y * v.y + v.z * v.z + v.w * v.w;
    #pragma unroll
    for (int off = 16; off > 0; off >>= 1) s += __shfl_xor_sync(~0u, s, off);
    if ((tid & 31) == 0) red[tid >> 5] = s;
    __syncthreads();
    if (tid == 0) g_wsq[n] = red[0] + red[1] + red[2] + red[3];
}

// z -> bf16 + zsq partials: d split in 4 chunks (blockIdx.z), 2 cols/thread
__global__ void __launch_bounds__(128)
convert_z_kernel(const float* __restrict__ z) {
    const int tid = threadIdx.x;
    const int b = blockIdx.y, col = blockIdx.x * 256 + tid * 2;
    const int dz = blockIdx.z, d0 = dz * 128;
    const bool valid = col < L_;            // L even -> pair co-valid
    const float* zp = z + (size_t)b * D_ * L_ + col;
    unsigned short* zo = g_zb + (size_t)b * D_ * L_ + col;
    float acc0 = 0.0f, acc1 = 0.0f;
    #pragma unroll 8
    for (int dd = 0; dd < 128; ++dd) {
        const int d = d0 + dd;
        float2 v = valid ? *reinterpret_cast<const float2*>(&zp[(size_t)d * L_])
                         : make_float2(0.f, 0.f);
        if (valid)
            *reinterpret_cast<uint32_t*>(&zo[(size_t)d * L_]) =
                (uint32_t)f2bf(v.x) | ((uint32_t)f2bf(v.y) << 16);
        acc0 = fmaf(v.x, v.x, acc0);
        acc1 = fmaf(v.y, v.y, acc1);
    }
    if (valid) {
        g_zsqp[dz][b * L_ + col]     = acc0;
        g_zsqp[dz][b * L_ + col + 1] = acc1;
    }
}

// =====================================================================
// Screen half: 512 codes (4 supertiles) x 128 cols; bf16 mma m16n8k16;
// K-chunk 64, 3-stage cp.async ring, one __syncthreads per k-iter.
// B fragments via ldmatrix.x4.trans (2 frags/instr).
// (byte-identical to confirmed 378.6us version)
// =====================================================================
#define AST   18432            // 128 * 144
#define BST   17408            // 64 * 272
#define BOFF  (3 * AST)
#define EOFF  (3 * (AST + BST))
#define SMEM_SCREEN (EOFF + 4608)

__device__ __forceinline__ void screen_issue(
    const unsigned short* __restrict__ zrow,
    uint32_t sbase, int t, int tid, int lb, int halfrow)
{
    const int nsup = t >> 3;
    const int kb = (t & 7) * 64;
    const int st = t % 3;
    #pragma unroll
    for (int i = 0; i < 4; ++i) {            // A: 128 rows x 8 chunks(16B)
        int v = tid + i * 256;
        int row = v >> 3, ch = v & 7;
        uint32_t dst = sbase + st * AST + row * 144 + ch * 16;
        const unsigned short* src =
            g_wb + (size_t)(halfrow + nsup * 128 + row) * D_ + kb + ch * 8;
        asm volatile("cp.async.cg.shared.global [%0], [%1], 16;"
                     :: "r"(dst), "l"(src) : "memory");
    }
    #pragma unroll
    for (int i = 0; i < 4; ++i) {            // B: 64 k-rows x 16 chunks
        int v = tid + i * 256;
        int kr = v >> 4, ch = v & 15;
        uint32_t dst = sbase + BOFF + st * BST + kr * 272 + ch * 16;
        const unsigned short* src = zrow + (size_t)(kb + kr) * L_ + lb + ch * 8;
        uint32_t ssz = (lb + ch * 8 < L_) ? 16u : 0u;
        asm volatile("cp.async.cg.shared.global [%0], [%1], 16, %2;"
                     :: "r"(dst), "l"(src), "r"(ssz) : "memory");
    }
    asm volatile("cp.async.commit_group;" ::: "memory");
}

__global__ void __launch_bounds__(256, 2)
screen_kernel()
{
    extern __shared__ char smc[];
    const uint32_t sbase = smem_u32(smc);
    float* ep  = (float*)(smc + EOFF);
    float* wv1 = ep;                 // [2][128]
    float* wv2 = ep + 256;
    int*   wi1 = (int*)(ep + 512);
    float* rv1 = ep + 768;
    float* rv2 = ep + 896;
    int*   ri1 = (int*)(ep + 1024);

    const int tid = threadIdx.x, lane = tid & 31, w = tid >> 5;
    const int mw = w >> 2, nw = w & 3;
    const int g = lane >> 2, cth = lane & 3;
    const int b = blockIdx.y, lb = blockIdx.x * 128;
    const int half = blockIdx.z;
    const int halfrow = half * 512;
    const unsigned short* zrow = g_zb + (size_t)b * D_ * L_;

    if (tid < 128) { rv1[tid] = -3.0e38f; rv2[tid] = -3.0e38f; ri1[tid] = 0; }

    const uint32_t offA  = (uint32_t)((lane & 15) * 144 + (lane >> 4) * 16);
    const uint32_t offB4 = (uint32_t)((lane & 15) * 272 + (lane >> 4) * 16);

    float c[4][4][4];

    screen_issue(zrow, sbase, 0, tid, lb, halfrow);
    screen_issue(zrow, sbase, 1, tid, lb, halfrow);

    for (int t = 0; t < 32; ++t) {
        const int kc = t & 7, nsup = t >> 3, st = t % 3;

        if (t < 30) asm volatile("cp.async.wait_group 1;" ::: "memory");
        else        asm volatile("cp.async.wait_group 0;" ::: "memory");
        __syncthreads();
        if (t < 30) screen_issue(zrow, sbase, t + 2, tid, lb, halfrow);

        if (kc == 0) {
            #pragma unroll
            for (int mt = 0; mt < 4; ++mt)
                #pragma unroll
                for (int nt = 0; nt < 4; ++nt)
                    #pragma unroll
                    for (int r = 0; r < 4; ++r) c[mt][nt][r] = 0.0f;
        }

        const uint32_t aB = sbase + st * AST;
        const uint32_t bB = sbase + BOFF + st * BST;
        #pragma unroll
        for (int q = 0; q < 4; ++q) {
            uint32_t af[4][4], bq[2][4];
            #pragma unroll
            for (int mt = 0; mt < 4; ++mt)
                LDMX4(af[mt], aB + (uint32_t)((mw * 64 + mt * 16) * 144 + q * 32) + offA);
            #pragma unroll
            for (int ntp = 0; ntp < 2; ++ntp)
                LDMX4T(bq[ntp], bB + (uint32_t)(q * 16 * 272 + nw * 64 + ntp * 32) + offB4);
            #pragma unroll
            for (int mt = 0; mt < 4; ++mt)
                #pragma unroll
                for (int nt = 0; nt < 4; ++nt)
                    MMA_BF16(c[mt][nt], af[mt], &bq[nt >> 1][(nt & 1) * 2]);
        }

        if (kc == 7) {
            // ---- supertile epilogue: per-column top-2 ----
            #pragma unroll
            for (int nt = 0; nt < 4; ++nt) {
                #pragma unroll
                for (int p = 0; p < 2; ++p) {
                    float v1 = -3.0e38f, v2 = -3.0e38f; int i1 = 0;
                    #pragma unroll
                    for (int mt = 0; mt < 4; ++mt)
                        #pragma unroll
                        for (int r = 0; r < 2; ++r) {
                            float v = c[mt][nt][r * 2 + p];
                            int code = halfrow + nsup * 128 + mw * 64 + mt * 16 + r * 8 + g;
                            if (v > v1) { v2 = v1; v1 = v; i1 = code; }
                            else if (v > v2) v2 = v;
                        }
                    #pragma unroll
                    for (int off = 4; off < 32; off <<= 1) {
                        float ov1 = __shfl_xor_sync(~0u, v1, off);
                        float ov2 = __shfl_xor_sync(~0u, v2, off);
                        int   oi1 = __shfl_xor_sync(~0u, i1, off);
                        if (ov1 > v1) { v2 = fmaxf(v1, ov2); v1 = ov1; i1 = oi1; }
                        else          { v2 = fmaxf(v2, ov1); }
                    }
                    if (g == 0) {
                        int col = nw * 32 + nt * 8 + 2 * cth + p;
                        wv1[mw * 128 + col] = v1;
                        wv2[mw * 128 + col] = v2;
                        wi1[mw * 128 + col] = i1;
                    }
                }
            }
            __syncthreads();
            if (tid < 128) {
                float a1 = wv1[tid], a2 = wv2[tid];             int ai = wi1[tid];
                float b1 = wv1[128 + tid], b2 = wv2[128 + tid]; int bi = wi1[128 + tid];
                float m1, m2; int mi;
                if (a1 >= b1) { m1 = a1; mi = ai; m2 = fmaxf(a2, b1); }
                else          { m1 = b1; mi = bi; m2 = fmaxf(b2, a1); }
                if (m1 > rv1[tid]) {
                    rv2[tid] = fmaxf(rv1[tid], m2);
                    rv1[tid] = m1; ri1[tid] = mi;
                } else {
                    rv2[tid] = fmaxf(rv2[tid], m1);
                }
            }
            __syncthreads();
        }
    }

    if (tid < 128) {
        int idx = b * LP + lb + tid;
        g_sv1[half][idx] = rv1[tid];
        g_sv2[half][idx] = rv2[tid];
        g_si1[half][idx] = ri1[tid];
    }
}

// ---- merge halves, flag narrow margins ----
__global__ void __launch_bounds__(256)
select_kernel()
{
    for (int s = blockIdx.x * blockDim.x + threadIdx.x; s < B_ * L_;
         s += gridDim.x * blockDim.x) {
        int b = s / L_, l = s % L_;
        int pidx = b * LP + l;
        float a1 = g_sv1[0][pidx], a2 = g_sv2[0][pidx]; int ai = g_si1[0][pidx];
        float b1 = g_sv1[1][pidx], b2 = g_sv2[1][pidx]; int bi = g_si1[1][pidx];
        float m1, m2; int mi;
        if (a1 >= b1) { m1 = a1; mi = ai; m2 = fmaxf(a2, b1); }
        else          { m1 = b1; mi = bi; m2 = fmaxf(b2, a1); }
        g_best[s] = mi;
        g_blog[s] = m1;
        if (m1 - m2 < DELTA) {
            int fs = atomicAdd(&g_flagcnt, 1);
            g_flaglist[fs] = (b << 16) | l;
        }
    }
}

// ---- gather flagged z columns into compact k-major matrix ----
__global__ void __launch_bounds__(256)
gather_kernel(const float* __restrict__ z)
{
    const int cnt = g_flagcnt;
    const int tid = threadIdx.x;
    for (int slot = blockIdx.x; slot < cnt; slot += gridDim.x) {
        int meta = g_flaglist[slot];
        int b = meta >> 16, l = meta & 0xFFFF;
        g_zg[(size_t)tid * CAPROW + slot] = z[((size_t)b * D_ + tid) * L_ + l];
        g_zg[(size_t)(tid + 256) * CAPROW + slot] =
            z[((size_t)b * D_ + tid + 256) * L_ + l];
    }
}

// ---- exact fp32 rescan of flagged columns (RLT=32: 2x items, half work) ----
__global__ void __launch_bounds__(256)
rescan_kernel(const float* __restrict__ W)
{
    __shared__ float Ws[32][128];
    __shared__ float Zs[32][RLT];
    __shared__ float pv[32][RLT];
    __shared__ int   pi[32][RLT];

    const int tid = threadIdx.x;
    const int tx = tid & 7, ty = tid >> 3;   // 8 col-groups(4) x 32 code-groups(4)
    const int cnt = g_flagcnt;
    const int tiles = (cnt + RLT - 1) / RLT;

    for (int item = blockIdx.x; item < tiles * NSLICE; item += gridDim.x) {
        const int ct = item / NSLICE, ns = item % NSLICE;
        const int cb = ct * RLT, nb = ns * 128;

        float acc[4][4];
        #pragma unroll
        for (int i = 0; i < 4; ++i)
            #pragma unroll
            for (int j = 0; j < 4; ++j) acc[i][j] = 0.0f;

        for (int kc = 0; kc < 16; ++kc) {
            const int kb = kc * 32;
            __syncthreads();
            #pragma unroll
            for (int p = 0; p < 4; ++p) {          // W tile 128 codes x 32 k
                int v = tid + p * 256;
                int n = v >> 3, kq = v & 7;
                float4 wv = *reinterpret_cast<const float4*>(
                    &W[(size_t)(nb + n) * D_ + kb + kq * 4]);
                Ws[kq * 4 + 0][n] = wv.x;
                Ws[kq * 4 + 1][n] = wv.y;
                Ws[kq * 4 + 2][n] = wv.z;
                Ws[kq * 4 + 3][n] = wv.w;
            }
            {                                      // Z tile 32 k x 32 cols
                int kr = tid >> 3, cq = tid & 7;
                float4 zv = *reinterpret_cast<const float4*>(
                    &g_zg[(size_t)(kb + kr) * CAPROW + cb + cq * 4]);
                *reinterpret_cast<float4*>(&Zs[kr][cq * 4]) = zv;
            }
            __syncthreads();
            #pragma unroll
            for (int k = 0; k < 32; ++k) {
                float4 wa = *reinterpret_cast<const float4*>(&Ws[k][ty * 4]);
                float4 za = *reinterpret_cast<const float4*>(&Zs[k][tx * 4]);
                float wf[4] = {wa.x, wa.y, wa.z, wa.w};
                float zf[4] = {za.x, za.y, za.z, za.w};
                #pragma unroll
                for (int i = 0; i < 4; ++i)
                    #pragma unroll
                    for (int j = 0; j < 4; ++j)
                        acc[i][j] = fmaf(wf[i], zf[j], acc[i][j]);
            }
        }
        __syncthreads();
        #pragma unroll
        for (int j = 0; j < 4; ++j) {
            float m = acc[0][j];
            int mi = nb + ty * 4;
            #pragma unroll
            for (int i = 1; i < 4; ++i) {
                float v = acc[i][j];
                if (v > m) { m = v; mi = nb + ty * 4 + i; }
            }
            pv[ty][tx * 4 + j] = m;
            pi[ty][tx * 4 + j] = mi;
        }
        __syncthreads();
        if (tid < RLT) {
            float m = pv[0][tid]; int mi = pi[0][tid];
            #pragma unroll
            for (int r = 1; r < 32; ++r) {
                float v = pv[r][tid]; int vi = pi[r][tid];
                if (v > m || (v == m && vi < mi)) { m = v; mi = vi; }
            }
            g_rpv[ns][cb + tid] = m;
            g_rpi[ns][cb + tid] = mi;
        }
        __syncthreads();
    }
}

__global__ void __launch_bounds__(256)
flagmerge_kernel()
{
    const int cnt = g_flagcnt;
    for (int s = blockIdx.x * blockDim.x + threadIdx.x; s < cnt;
         s += gridDim.x * blockDim.x) {
        float bv = g_rpv[0][s]; int bi = g_rpi[0][s];
        #pragma unroll
        for (int r = 1; r < NSLICE; ++r) {
            float v = g_rpv[r][s];
            if (v > bv) { bv = v; bi = g_rpi[r][s]; }
        }
        int meta = g_flaglist[s];
        int bl = (meta >> 16) * L_ + (meta & 0xFFFF);
        g_best[bl] = bi;
        g_blog[bl] = bv;
    }
}

// ---- output: ind + z_q gather; d split across blockIdx.y (8x CTAs) ----
#define OW_SMEM (256 * 65 * 4)
__global__ void __launch_bounds__(256)
output_kernel(const float* __restrict__ W, float* __restrict__ out)
{
    extern __shared__ float sw[];          // [256][65]
    __shared__ int besti[256];
    const int tid = threadIdx.x, lane = tid & 31, w = tid >> 5;
    const int b = blockIdx.x / 12, lt = blockIdx.x % 12;
    const int d0 = blockIdx.y * 64;
    const int lbase = lt * 256;
    const int valid = (L_ - lbase < 256) ? (L_ - lbase) : 256;

    {
        int bi = 0;
        if (tid < valid) {
            bi = g_best[b * L_ + lbase + tid];
            if (blockIdx.y == 0)
                out[ZQ_ELEMS + (size_t)b * L_ + lbase + tid] = (float)bi;
        }
        besti[tid] = bi;
    }
    __syncthreads();

    #pragma unroll
    for (int cs = 0; cs < 32; ++cs) {
        int col = w * 32 + cs;
        const float2 wv = *reinterpret_cast<const float2*>(
            &W[(size_t)besti[col] * D_ + d0 + lane * 2]);
        sw[col * 65 + lane * 2]     = wv.x;
        sw[col * 65 + lane * 2 + 1] = wv.y;
    }
    __syncthreads();
    #pragma unroll 8
    for (int it = 0; it < 64; ++it) {
        int idx = it * 256 + tid;
        int col = idx & 255;
        int dl = idx >> 8;
        if (col < valid) {
            out[((size_t)b * D_ + d0 + dl) * L_ + lbase + col] =
                sw[col * 65 + dl];
        }
    }
}

// ---- loss via identity: wsq[ind] - 2*logit + sum(zsq partials) ----
__global__ void __launch_bounds__(256)
loss_kernel()
{
    __shared__ double red[256];
    const int tid = threadIdx.x;
    double lsum = 0.0;
    for (int s = blockIdx.x * blockDim.x + tid; s < B_ * L_;
         s += gridDim.x * blockDim.x) {
        float zsq = (g_zsqp[0][s] + g_zsqp[1][s]) + (g_zsqp[2][s] + g_zsqp[3][s]);
        lsum += (double)g_wsq[g_best[s]] - 2.0 * (double)g_blog[s] + (double)zsq;
    }
    red[tid] = lsum;
    __syncthreads();
    #pragma unroll
    for (int s = 128; s > 0; s >>= 1) {
        if (tid < s) red[tid] += red[tid + s];
        __syncthreads();
    }
    if (tid == 0) atomicAdd(&g_loss, red[0]);
}

extern "C" void kernel_launch(void* const* d_in, const int* in_sizes, int n_in,
                              void* d_out, int out_size) {
    const float* z = (const float*)d_in[0];
    const float* W = (const float*)d_in[1];
    if (n_in >= 2 && in_sizes[0] == NE_ * D_) {
        z = (const float*)d_in[1];
        W = (const float*)d_in[0];
    }
    float* out = (float*)d_out;

    cudaFuncSetAttribute(screen_kernel,
                         cudaFuncAttributeMaxDynamicSharedMemorySize, SMEM_SCREEN);
    cudaFuncSetAttribute(output_kernel,
                         cudaFuncAttributeMaxDynamicSharedMemorySize, OW_SMEM);

    init_kernel<<<1, 1>>>();
    convert_w_kernel<<<NE_, 128>>>(W);
    {
        dim3 grd((L_ + 255) / 256, B_, 4);
        convert_z_kernel<<<grd, 128>>>(z);
    }
    {
        dim3 grd((L_ + 127) / 128, B_, 2);
        screen_kernel<<<grd, 256, SMEM_SCREEN>>>();
    }
    select_kernel<<<96, 256>>>();
    gather_kernel<<<256, 256>>>(z);
    rescan_kernel<<<512, 256>>>(W);
    flagmerge_kernel<<<64, 256>>>();
    {
        dim3 grd(B_ * 12, 8);
        output_kernel<<<grd, 256, OW_SMEM>>>(W, out);
    }
    loss_kernel<<<96, 256>>>();
    finalize_kernel<<<1, 1>>>(out);
}